// round 13
// baseline (speedup 1.0000x reference)
#include <cuda_runtime.h>
#include <math.h>

#define W 512
#define H 512
#define HW (H * W)          // 262144
#define EW (HW / 8)         // 32768 threads in finalize, 8 px each
#define TWO_PI 6.283185307179586f
#define ALPHA_THRESH (1.0f / 255.0f)

// Interleaved accumulation plane: (c0, c1, c2, junk) per pixel.
// Zero-initialized BSS; finalize re-zeroes it every replay.
__device__ float4 g_accum[HW];

__global__ __launch_bounds__(256) void splat_kernel(
        const float* __restrict__ xyz,
        const float* __restrict__ scaling,
        const float* __restrict__ rot,
        const float* __restrict__ feat,
        const float* __restrict__ opac,
        int n) {
    int g = (blockIdx.x * blockDim.x + threadIdx.x) >> 5;
    int lane = threadIdx.x & 31;

    if (g < n) {
        // Per-gaussian prep (all lanes redundantly; loads broadcast via L1)
        float2 xy = ((const float2*)xyz)[g];
        float2 sc = ((const float2*)scaling)[g];
        float mx = tanhf(xy.x);
        float my = tanhf(xy.y);
        float sx = fabsf(sc.x + 0.5f);
        float sy = fabsf(sc.y + 0.5f);
        float theta = (1.0f / (1.0f + expf(-rot[g]))) * TWO_PI;

        float cx = 0.5f * ((mx + 1.0f) * (float)W - 1.0f);
        float cy = 0.5f * ((my + 1.0f) * (float)H - 1.0f);

        float sth, cth;
        sincosf(theta, &sth, &cth);
        float sx2 = sx * sx;
        float sy2 = sy * sy;
        float a = cth * cth * sx2 + sth * sth * sy2;
        float b = cth * sth * (sx2 - sy2);
        float c = sth * sth * sx2 + cth * cth * sy2;
        float det = a * c - b * b;
        float op = opac[g];
        float tmax = logf(op * 255.0f);     // alpha > 1/255 <=> sigma < tmax

        if (det > 0.0f && tmax > 0.0f) {
            float inv_det = 1.0f / fmaxf(det, 1e-12f);
            float hA = 0.5f * c * inv_det;      // 0.5*A
            float B  = -b * inv_det;
            float hC = 0.5f * a * inv_det;      // 0.5*C

            // a,c <= 2.25, tmax <= ln(255) => rx,ry <= ~6.1 => bbox width <= 13 < 16
            float rx = sqrtf(2.0f * tmax * a) + 1.0f;
            float ry = sqrtf(2.0f * tmax * c) + 1.0f;

            int x0 = max(0, (int)ceilf(cx - rx));
            int x1 = min(W - 1, (int)floorf(cx + rx));
            int y0 = max(0, (int)ceilf(cy - ry));
            int y1 = min(H - 1, (int)floorf(cy + ry));

            if (x1 >= x0 && y1 >= y0) {
                float c0 = op * feat[3 * g];
                float c1 = op * feat[3 * g + 1];
                float c2 = op * feat[3 * g + 2];

                // lanes 0-15: even rows, lanes 16-31: odd rows; lane&15 indexes x
                int px = x0 + (lane & 15);
                float dx = cx - (float)px;
                float sxx = hA * dx * dx;
                float bdx = B * dx;
                bool xin = (px <= x1);

                for (int py = y0 + (lane >> 4); py <= y1; py += 2) {
                    float dy = cy - (float)py;
                    float sigma = fmaf(hC, dy, bdx) * dy + sxx;
                    float w = __expf(-sigma);
                    float alpha = op * w;
                    if (xin && sigma >= 0.0f && alpha > ALPHA_THRESH) {
                        float4* dst = &g_accum[py * W + px];
                        asm volatile("red.global.add.v4.f32 [%0], {%1, %2, %3, %4};"
                                     :: "l"(dst), "f"(w * c0), "f"(w * c1),
                                        "f"(w * c2), "f"(0.0f)
                                     : "memory");
                    }
                }
            }
        }
    }

    // allow the dependent finalize kernel to launch/ramp now
    asm volatile("griddepcontrol.launch_dependents;");
}

__global__ __launch_bounds__(256) void finalize_kernel(float* __restrict__ out) {
    int t = blockIdx.x * blockDim.x + threadIdx.x;   // 32768 threads, 8 px each

    // wait until splat's memory is visible
    asm volatile("griddepcontrol.wait;");

    // 8 independent L2-only loads up front -> MLP = 8 per thread
    float4 v0 = __ldcg(&g_accum[t]);
    float4 v1 = __ldcg(&g_accum[t + EW]);
    float4 v2 = __ldcg(&g_accum[t + 2 * EW]);
    float4 v3 = __ldcg(&g_accum[t + 3 * EW]);
    float4 v4 = __ldcg(&g_accum[t + 4 * EW]);
    float4 v5 = __ldcg(&g_accum[t + 5 * EW]);
    float4 v6 = __ldcg(&g_accum[t + 6 * EW]);
    float4 v7 = __ldcg(&g_accum[t + 7 * EW]);

    float4 z = make_float4(0.0f, 0.0f, 0.0f, 0.0f);
    g_accum[t]          = z;           // re-arm for next graph replay
    g_accum[t + EW]     = z;
    g_accum[t + 2 * EW] = z;
    g_accum[t + 3 * EW] = z;
    g_accum[t + 4 * EW] = z;
    g_accum[t + 5 * EW] = z;
    g_accum[t + 6 * EW] = z;
    g_accum[t + 7 * EW] = z;

    #define CLAMP(x) fminf(fmaxf((x), 0.0f), 1.0f)
    #define EMIT(v, off) do {                                   \
        __stcs(&out[(off) + t],           CLAMP((v).x));        \
        __stcs(&out[HW + (off) + t],      CLAMP((v).y));        \
        __stcs(&out[2 * HW + (off) + t],  CLAMP((v).z));        \
    } while (0)

    EMIT(v0, 0);
    EMIT(v1, EW);
    EMIT(v2, 2 * EW);
    EMIT(v3, 3 * EW);
    EMIT(v4, 4 * EW);
    EMIT(v5, 5 * EW);
    EMIT(v6, 6 * EW);
    EMIT(v7, 7 * EW);
    #undef EMIT
    #undef CLAMP
}

extern "C" void kernel_launch(void* const* d_in, const int* in_sizes, int n_in,
                              void* d_out, int out_size) {
    const float* xyz     = (const float*)d_in[0];  // (N,2)
    const float* scaling = (const float*)d_in[1];  // (N,2)
    const float* rot     = (const float*)d_in[2];  // (N,1)
    const float* feat    = (const float*)d_in[3];  // (N,3)
    const float* opac    = (const float*)d_in[4];  // (N,1)
    float* out = (float*)d_out;                     // (1,3,512,512)

    int n = in_sizes[0] / 2;

    int blocks = (n + 7) / 8;                       // 8 warps/block, 1 gaussian/warp
    splat_kernel<<<blocks, 256>>>(xyz, scaling, rot, feat, opac, n);

    // finalize launched as a programmatic dependent: ramps while splat runs
    cudaLaunchConfig_t cfg = {};
    cfg.gridDim  = dim3(EW / 256);                  // 128 blocks
    cfg.blockDim = dim3(256);
    cfg.dynamicSmemBytes = 0;
    cfg.stream = 0;
    cudaLaunchAttribute attr[1];
    attr[0].id = cudaLaunchAttributeProgrammaticStreamSerialization;
    attr[0].val.programmaticStreamSerializationAllowed = 1;
    cfg.attrs = attr;
    cfg.numAttrs = 1;
    cudaLaunchKernelEx(&cfg, finalize_kernel, out);
}

// round 14
// speedup vs baseline: 1.0029x; 1.0029x over previous
#include <cuda_runtime.h>
#include <math.h>

#define W 512
#define H 512
#define HW (H * W)          // 262144
#define QW (HW / 4)         // 65536
#define TWO_PI 6.283185307179586f
#define ALPHA_THRESH (1.0f / 255.0f)

// Interleaved accumulation plane: (c0, c1, c2, junk) per pixel.
// Zero-initialized BSS; finalize re-zeroes it every replay.
__device__ float4 g_accum[HW];

__global__ __launch_bounds__(256) void splat_kernel(
        const float* __restrict__ xyz,
        const float* __restrict__ scaling,
        const float* __restrict__ rot,
        const float* __restrict__ feat,
        const float* __restrict__ opac,
        int n) {
    int g = (blockIdx.x * blockDim.x + threadIdx.x) >> 5;
    int lane = threadIdx.x & 31;

    if (g < n) {
        // Per-gaussian prep with MUFU-direct intrinsics (short dependency chain)
        float2 xy = ((const float2*)xyz)[g];
        float2 sc = ((const float2*)scaling)[g];

        // tanh(x) = 1 - 2/(exp(2x)+1)
        float mx = 1.0f - __fdividef(2.0f, __expf(2.0f * xy.x) + 1.0f);
        float my = 1.0f - __fdividef(2.0f, __expf(2.0f * xy.y) + 1.0f);
        float sx = fabsf(sc.x + 0.5f);
        float sy = fabsf(sc.y + 0.5f);
        // sigmoid(r) * 2pi
        float theta = __fdividef(TWO_PI, 1.0f + __expf(-rot[g]));

        float cx = 0.5f * ((mx + 1.0f) * (float)W - 1.0f);
        float cy = 0.5f * ((my + 1.0f) * (float)H - 1.0f);

        float sth, cth;
        __sincosf(theta, &sth, &cth);
        float sx2 = sx * sx;
        float sy2 = sy * sy;
        float a = cth * cth * sx2 + sth * sth * sy2;
        float b = cth * sth * (sx2 - sy2);
        float c = sth * sth * sx2 + cth * cth * sy2;
        float det = a * c - b * b;
        float op = opac[g];
        float tmax = __logf(op * 255.0f);   // alpha > 1/255 <=> sigma < tmax

        if (det > 0.0f && tmax > 0.0f) {
            float inv_det = __fdividef(1.0f, fmaxf(det, 1e-12f));
            float hA = 0.5f * c * inv_det;      // 0.5*A
            float B  = -b * inv_det;
            float hC = 0.5f * a * inv_det;      // 0.5*C

            // a,c <= 2.25, tmax <= ln(255) => rx,ry <= ~6.1 => bbox width <= 13 < 16
            float rx = sqrtf(2.0f * tmax * a) + 1.0f;
            float ry = sqrtf(2.0f * tmax * c) + 1.0f;

            int x0 = max(0, (int)ceilf(cx - rx));
            int x1 = min(W - 1, (int)floorf(cx + rx));
            int y0 = max(0, (int)ceilf(cy - ry));
            int y1 = min(H - 1, (int)floorf(cy + ry));

            if (x1 >= x0 && y1 >= y0) {
                float c0 = op * feat[3 * g];
                float c1 = op * feat[3 * g + 1];
                float c2 = op * feat[3 * g + 2];

                // lanes 0-15: even rows, lanes 16-31: odd rows; lane&15 indexes x
                int px = x0 + (lane & 15);
                float dx = cx - (float)px;
                float sxx = hA * dx * dx;
                float bdx = B * dx;
                bool xin = (px <= x1);

                for (int py = y0 + (lane >> 4); py <= y1; py += 2) {
                    float dy = cy - (float)py;
                    float sigma = fmaf(hC, dy, bdx) * dy + sxx;
                    float w = __expf(-sigma);
                    float alpha = op * w;
                    if (xin && sigma >= 0.0f && alpha > ALPHA_THRESH) {
                        float4* dst = &g_accum[py * W + px];
                        asm volatile("red.global.add.v4.f32 [%0], {%1, %2, %3, %4};"
                                     :: "l"(dst), "f"(w * c0), "f"(w * c1),
                                        "f"(w * c2), "f"(0.0f)
                                     : "memory");
                    }
                }
            }
        }
    }

    // allow the dependent finalize kernel to launch/ramp now
    asm volatile("griddepcontrol.launch_dependents;");
}

__global__ __launch_bounds__(256) void finalize_kernel(float* __restrict__ out) {
    int t = blockIdx.x * blockDim.x + threadIdx.x;   // 65536 threads, 4 px each

    // wait until splat's memory is visible
    asm volatile("griddepcontrol.wait;");

    // 4 independent loads up front -> MLP = 4 per thread
    float4 v0 = __ldcg(&g_accum[t]);
    float4 v1 = __ldcg(&g_accum[t + QW]);
    float4 v2 = __ldcg(&g_accum[t + 2 * QW]);
    float4 v3 = __ldcg(&g_accum[t + 3 * QW]);

    float4 z = make_float4(0.0f, 0.0f, 0.0f, 0.0f);
    g_accum[t]          = z;           // re-arm for next graph replay
    g_accum[t + QW]     = z;
    g_accum[t + 2 * QW] = z;
    g_accum[t + 3 * QW] = z;

    #define CLAMP(x) fminf(fmaxf((x), 0.0f), 1.0f)
    __stcs(&out[t],                    CLAMP(v0.x));
    __stcs(&out[t + QW],               CLAMP(v1.x));
    __stcs(&out[t + 2 * QW],           CLAMP(v2.x));
    __stcs(&out[t + 3 * QW],           CLAMP(v3.x));

    __stcs(&out[HW + t],               CLAMP(v0.y));
    __stcs(&out[HW + t + QW],          CLAMP(v1.y));
    __stcs(&out[HW + t + 2 * QW],      CLAMP(v2.y));
    __stcs(&out[HW + t + 3 * QW],      CLAMP(v3.y));

    __stcs(&out[2 * HW + t],           CLAMP(v0.z));
    __stcs(&out[2 * HW + t + QW],      CLAMP(v1.z));
    __stcs(&out[2 * HW + t + 2 * QW],  CLAMP(v2.z));
    __stcs(&out[2 * HW + t + 3 * QW],  CLAMP(v3.z));
    #undef CLAMP
}

extern "C" void kernel_launch(void* const* d_in, const int* in_sizes, int n_in,
                              void* d_out, int out_size) {
    const float* xyz     = (const float*)d_in[0];  // (N,2)
    const float* scaling = (const float*)d_in[1];  // (N,2)
    const float* rot     = (const float*)d_in[2];  // (N,1)
    const float* feat    = (const float*)d_in[3];  // (N,3)
    const float* opac    = (const float*)d_in[4];  // (N,1)
    float* out = (float*)d_out;                     // (1,3,512,512)

    int n = in_sizes[0] / 2;

    int blocks = (n + 7) / 8;                       // 8 warps/block, 1 gaussian/warp
    splat_kernel<<<blocks, 256>>>(xyz, scaling, rot, feat, opac, n);

    // finalize launched as a programmatic dependent: ramps while splat runs
    cudaLaunchConfig_t cfg = {};
    cfg.gridDim  = dim3(QW / 256);                  // 256 blocks
    cfg.blockDim = dim3(256);
    cfg.dynamicSmemBytes = 0;
    cfg.stream = 0;
    cudaLaunchAttribute attr[1];
    attr[0].id = cudaLaunchAttributeProgrammaticStreamSerialization;
    attr[0].val.programmaticStreamSerializationAllowed = 1;
    cfg.attrs = attr;
    cfg.numAttrs = 1;
    cudaLaunchKernelEx(&cfg, finalize_kernel, out);
}

// round 15
// speedup vs baseline: 1.0269x; 1.0239x over previous
#include <cuda_runtime.h>
#include <math.h>

#define W 512
#define H 512
#define HW (H * W)          // 262144
#define QW (HW / 4)         // 65536
#define TWO_PI 6.283185307179586f
#define ALPHA_THRESH (1.0f / 255.0f)

// Interleaved accumulation plane: (c0, c1, c2, junk) per pixel.
// Zero-initialized BSS; finalize re-zeroes it every replay.
__device__ float4 g_accum[HW];

__global__ __launch_bounds__(256) void splat_kernel(
        const float* __restrict__ xyz,
        const float* __restrict__ scaling,
        const float* __restrict__ rot,
        const float* __restrict__ feat,
        const float* __restrict__ opac,
        int n) {
    // Signal dependent launch IMMEDIATELY: finalize's grid launches and ramps
    // concurrently with splat's work; its griddepcontrol.wait still blocks
    // until this grid's memory is flushed, so ordering is preserved.
    asm volatile("griddepcontrol.launch_dependents;");

    int g = (blockIdx.x * blockDim.x + threadIdx.x) >> 5;
    int lane = threadIdx.x & 31;
    if (g >= n) return;

    // Per-gaussian prep with MUFU-direct intrinsics (short dependency chain)
    float2 xy = ((const float2*)xyz)[g];
    float2 sc = ((const float2*)scaling)[g];

    // tanh(x) = 1 - 2/(exp(2x)+1)
    float mx = 1.0f - __fdividef(2.0f, __expf(2.0f * xy.x) + 1.0f);
    float my = 1.0f - __fdividef(2.0f, __expf(2.0f * xy.y) + 1.0f);
    float sx = fabsf(sc.x + 0.5f);
    float sy = fabsf(sc.y + 0.5f);
    // sigmoid(r) * 2pi
    float theta = __fdividef(TWO_PI, 1.0f + __expf(-rot[g]));

    float cx = 0.5f * ((mx + 1.0f) * (float)W - 1.0f);
    float cy = 0.5f * ((my + 1.0f) * (float)H - 1.0f);

    float sth, cth;
    __sincosf(theta, &sth, &cth);
    float sx2 = sx * sx;
    float sy2 = sy * sy;
    float a = cth * cth * sx2 + sth * sth * sy2;
    float b = cth * sth * (sx2 - sy2);
    float c = sth * sth * sx2 + cth * cth * sy2;
    float det = a * c - b * b;
    float op = opac[g];
    float tmax = __logf(op * 255.0f);   // alpha > 1/255 <=> sigma < tmax
    if (!(det > 0.0f) || !(tmax > 0.0f)) return;

    float inv_det = __fdividef(1.0f, fmaxf(det, 1e-12f));
    float hA = 0.5f * c * inv_det;      // 0.5*A
    float B  = -b * inv_det;
    float hC = 0.5f * a * inv_det;      // 0.5*C

    // a,c <= 2.25, tmax <= ln(255) => rx,ry <= ~6.1 => bbox width <= 13 < 16
    float rx = sqrtf(2.0f * tmax * a) + 1.0f;
    float ry = sqrtf(2.0f * tmax * c) + 1.0f;

    int x0 = max(0, (int)ceilf(cx - rx));
    int x1 = min(W - 1, (int)floorf(cx + rx));
    int y0 = max(0, (int)ceilf(cy - ry));
    int y1 = min(H - 1, (int)floorf(cy + ry));
    if (x1 < x0 || y1 < y0) return;

    float c0 = op * feat[3 * g];
    float c1 = op * feat[3 * g + 1];
    float c2 = op * feat[3 * g + 2];

    // lanes 0-15: even rows, lanes 16-31: odd rows; lane&15 indexes x
    int px = x0 + (lane & 15);
    float dx = cx - (float)px;
    float sxx = hA * dx * dx;
    float bdx = B * dx;
    bool xin = (px <= x1);

    for (int py = y0 + (lane >> 4); py <= y1; py += 2) {
        float dy = cy - (float)py;
        float sigma = fmaf(hC, dy, bdx) * dy + sxx;
        float w = __expf(-sigma);
        float alpha = op * w;
        if (xin && sigma >= 0.0f && alpha > ALPHA_THRESH) {
            float4* dst = &g_accum[py * W + px];
            asm volatile("red.global.add.v4.f32 [%0], {%1, %2, %3, %4};"
                         :: "l"(dst), "f"(w * c0), "f"(w * c1),
                            "f"(w * c2), "f"(0.0f)
                         : "memory");
        }
    }
}

__global__ __launch_bounds__(256) void finalize_kernel(float* __restrict__ out) {
    int t = blockIdx.x * blockDim.x + threadIdx.x;   // 65536 threads, 4 px each

    // wait until splat's memory is visible
    asm volatile("griddepcontrol.wait;");

    // 4 independent L2-only loads up front -> MLP = 4 per thread
    float4 v0 = __ldcg(&g_accum[t]);
    float4 v1 = __ldcg(&g_accum[t + QW]);
    float4 v2 = __ldcg(&g_accum[t + 2 * QW]);
    float4 v3 = __ldcg(&g_accum[t + 3 * QW]);

    float4 z = make_float4(0.0f, 0.0f, 0.0f, 0.0f);
    g_accum[t]          = z;           // re-arm for next graph replay
    g_accum[t + QW]     = z;
    g_accum[t + 2 * QW] = z;
    g_accum[t + 3 * QW] = z;

    #define CLAMP(x) fminf(fmaxf((x), 0.0f), 1.0f)
    __stcs(&out[t],                    CLAMP(v0.x));
    __stcs(&out[t + QW],               CLAMP(v1.x));
    __stcs(&out[t + 2 * QW],           CLAMP(v2.x));
    __stcs(&out[t + 3 * QW],           CLAMP(v3.x));

    __stcs(&out[HW + t],               CLAMP(v0.y));
    __stcs(&out[HW + t + QW],          CLAMP(v1.y));
    __stcs(&out[HW + t + 2 * QW],      CLAMP(v2.y));
    __stcs(&out[HW + t + 3 * QW],      CLAMP(v3.y));

    __stcs(&out[2 * HW + t],           CLAMP(v0.z));
    __stcs(&out[2 * HW + t + QW],      CLAMP(v1.z));
    __stcs(&out[2 * HW + t + 2 * QW],  CLAMP(v2.z));
    __stcs(&out[2 * HW + t + 3 * QW],  CLAMP(v3.z));
    #undef CLAMP
}

extern "C" void kernel_launch(void* const* d_in, const int* in_sizes, int n_in,
                              void* d_out, int out_size) {
    const float* xyz     = (const float*)d_in[0];  // (N,2)
    const float* scaling = (const float*)d_in[1];  // (N,2)
    const float* rot     = (const float*)d_in[2];  // (N,1)
    const float* feat    = (const float*)d_in[3];  // (N,3)
    const float* opac    = (const float*)d_in[4];  // (N,1)
    float* out = (float*)d_out;                     // (1,3,512,512)

    int n = in_sizes[0] / 2;

    int blocks = (n + 7) / 8;                       // 8 warps/block, 1 gaussian/warp
    splat_kernel<<<blocks, 256>>>(xyz, scaling, rot, feat, opac, n);

    // finalize launched as a programmatic dependent: ramps while splat runs
    cudaLaunchConfig_t cfg = {};
    cfg.gridDim  = dim3(QW / 256);                  // 256 blocks
    cfg.blockDim = dim3(256);
    cfg.dynamicSmemBytes = 0;
    cfg.stream = 0;
    cudaLaunchAttribute attr[1];
    attr[0].id = cudaLaunchAttributeProgrammaticStreamSerialization;
    attr[0].val.programmaticStreamSerializationAllowed = 1;
    cfg.attrs = attr;
    cfg.numAttrs = 1;
    cudaLaunchKernelEx(&cfg, finalize_kernel, out);
}

// round 16
// speedup vs baseline: 1.0299x; 1.0030x over previous
#include <cuda_runtime.h>
#include <math.h>

#define W 512
#define H 512
#define HW (H * W)          // 262144
#define QW (HW / 4)         // 65536
#define TWO_PI 6.283185307179586f
#define ALPHA_THRESH (1.0f / 255.0f)

// Interleaved accumulation plane: (c0, c1, c2, junk) per pixel.
// Zero-initialized BSS; finalize re-zeroes it every replay.
__device__ float4 g_accum[HW];

__global__ __launch_bounds__(256) void splat_kernel(
        const float* __restrict__ xyz,
        const float* __restrict__ scaling,
        const float* __restrict__ rot,
        const float* __restrict__ feat,
        const float* __restrict__ opac,
        int n) {
    // Signal dependent launch immediately: finalize's grid ramps concurrently.
    asm volatile("griddepcontrol.launch_dependents;");

    // Half-warp per gaussian: lanes 0-15 -> g0, lanes 16-31 -> g1.
    int warp = (blockIdx.x * blockDim.x + threadIdx.x) >> 5;
    int lane = threadIdx.x & 31;
    int g = warp * 2 + (lane >> 4);
    if (g >= n) return;

    // Per-gaussian prep with MUFU-direct intrinsics; both half-warps' preps
    // execute in the same SIMT pass (prep cost per gaussian halves vs 1/warp).
    float2 xy = ((const float2*)xyz)[g];
    float2 sc = ((const float2*)scaling)[g];

    // tanh(x) = 1 - 2/(exp(2x)+1)
    float mx = 1.0f - __fdividef(2.0f, __expf(2.0f * xy.x) + 1.0f);
    float my = 1.0f - __fdividef(2.0f, __expf(2.0f * xy.y) + 1.0f);
    float sx = fabsf(sc.x + 0.5f);
    float sy = fabsf(sc.y + 0.5f);
    // sigmoid(r) * 2pi
    float theta = __fdividef(TWO_PI, 1.0f + __expf(-rot[g]));

    float cx = 0.5f * ((mx + 1.0f) * (float)W - 1.0f);
    float cy = 0.5f * ((my + 1.0f) * (float)H - 1.0f);

    float sth, cth;
    __sincosf(theta, &sth, &cth);
    float sx2 = sx * sx;
    float sy2 = sy * sy;
    float a = cth * cth * sx2 + sth * sth * sy2;
    float b = cth * sth * (sx2 - sy2);
    float c = sth * sth * sx2 + cth * cth * sy2;
    float det = a * c - b * b;
    float op = opac[g];
    float tmax = __logf(op * 255.0f);   // alpha > 1/255 <=> sigma < tmax
    if (!(det > 0.0f) || !(tmax > 0.0f)) return;

    float inv_det = __fdividef(1.0f, fmaxf(det, 1e-12f));
    float hA = 0.5f * c * inv_det;      // 0.5*A
    float B  = -b * inv_det;
    float hC = 0.5f * a * inv_det;      // 0.5*C

    // a,c <= 2.25, tmax <= ln(255) => rx,ry <= ~6.1 => bbox width <= 13 < 16
    float rx = sqrtf(2.0f * tmax * a) + 1.0f;
    float ry = sqrtf(2.0f * tmax * c) + 1.0f;

    int x0 = max(0, (int)ceilf(cx - rx));
    int x1 = min(W - 1, (int)floorf(cx + rx));
    int y0 = max(0, (int)ceilf(cy - ry));
    int y1 = min(H - 1, (int)floorf(cy + ry));
    if (x1 < x0 || y1 < y0) return;

    float c0 = op * feat[3 * g];
    float c1 = op * feat[3 * g + 1];
    float c2 = op * feat[3 * g + 2];

    // lane&15 indexes x within this gaussian's bbox; loop rows one at a time.
    int px = x0 + (lane & 15);
    float dx = cx - (float)px;
    float sxx = hA * dx * dx;
    float bdx = B * dx;
    bool xin = (px <= x1);

    for (int py = y0; py <= y1; py++) {
        float dy = cy - (float)py;
        float sigma = fmaf(hC, dy, bdx) * dy + sxx;
        float w = __expf(-sigma);
        float alpha = op * w;
        if (xin && sigma >= 0.0f && alpha > ALPHA_THRESH) {
            float4* dst = &g_accum[py * W + px];
            asm volatile("red.global.add.v4.f32 [%0], {%1, %2, %3, %4};"
                         :: "l"(dst), "f"(w * c0), "f"(w * c1),
                            "f"(w * c2), "f"(0.0f)
                         : "memory");
        }
    }
}

__global__ __launch_bounds__(256) void finalize_kernel(float* __restrict__ out) {
    int t = blockIdx.x * blockDim.x + threadIdx.x;   // 65536 threads, 4 px each

    // wait until splat's memory is visible
    asm volatile("griddepcontrol.wait;");

    // 4 independent L2-only loads up front -> MLP = 4 per thread
    float4 v0 = __ldcg(&g_accum[t]);
    float4 v1 = __ldcg(&g_accum[t + QW]);
    float4 v2 = __ldcg(&g_accum[t + 2 * QW]);
    float4 v3 = __ldcg(&g_accum[t + 3 * QW]);

    float4 z = make_float4(0.0f, 0.0f, 0.0f, 0.0f);
    g_accum[t]          = z;           // re-arm for next graph replay
    g_accum[t + QW]     = z;
    g_accum[t + 2 * QW] = z;
    g_accum[t + 3 * QW] = z;

    #define CLAMP(x) fminf(fmaxf((x), 0.0f), 1.0f)
    __stcs(&out[t],                    CLAMP(v0.x));
    __stcs(&out[t + QW],               CLAMP(v1.x));
    __stcs(&out[t + 2 * QW],           CLAMP(v2.x));
    __stcs(&out[t + 3 * QW],           CLAMP(v3.x));

    __stcs(&out[HW + t],               CLAMP(v0.y));
    __stcs(&out[HW + t + QW],          CLAMP(v1.y));
    __stcs(&out[HW + t + 2 * QW],      CLAMP(v2.y));
    __stcs(&out[HW + t + 3 * QW],      CLAMP(v3.y));

    __stcs(&out[2 * HW + t],           CLAMP(v0.z));
    __stcs(&out[2 * HW + t + QW],      CLAMP(v1.z));
    __stcs(&out[2 * HW + t + 2 * QW],  CLAMP(v2.z));
    __stcs(&out[2 * HW + t + 3 * QW],  CLAMP(v3.z));
    #undef CLAMP
}

extern "C" void kernel_launch(void* const* d_in, const int* in_sizes, int n_in,
                              void* d_out, int out_size) {
    const float* xyz     = (const float*)d_in[0];  // (N,2)
    const float* scaling = (const float*)d_in[1];  // (N,2)
    const float* rot     = (const float*)d_in[2];  // (N,1)
    const float* feat    = (const float*)d_in[3];  // (N,3)
    const float* opac    = (const float*)d_in[4];  // (N,1)
    float* out = (float*)d_out;                     // (1,3,512,512)

    int n = in_sizes[0] / 2;

    int blocks = (n + 15) / 16;                     // 8 warps/block, 2 gaussians/warp
    splat_kernel<<<blocks, 256>>>(xyz, scaling, rot, feat, opac, n);

    // finalize launched as a programmatic dependent: ramps while splat runs
    cudaLaunchConfig_t cfg = {};
    cfg.gridDim  = dim3(QW / 256);                  // 256 blocks
    cfg.blockDim = dim3(256);
    cfg.dynamicSmemBytes = 0;
    cfg.stream = 0;
    cudaLaunchAttribute attr[1];
    attr[0].id = cudaLaunchAttributeProgrammaticStreamSerialization;
    attr[0].val.programmaticStreamSerializationAllowed = 1;
    cfg.attrs = attr;
    cfg.numAttrs = 1;
    cudaLaunchKernelEx(&cfg, finalize_kernel, out);
}

// round 17
// speedup vs baseline: 1.0750x; 1.0438x over previous
#include <cuda_runtime.h>
#include <math.h>

#define W 512
#define H 512
#define HW (H * W)          // 262144
#define QW (HW / 4)         // 65536
#define TWO_PI 6.283185307179586f
#define ALPHA_THRESH (1.0f / 255.0f)

// Interleaved accumulation plane: (c0, c1, c2, junk) per pixel.
// Zero-initialized BSS; finalize re-zeroes it every replay.
__device__ float4 g_accum[HW];

__global__ __launch_bounds__(256) void splat_kernel(
        const float* __restrict__ xyz,
        const float* __restrict__ scaling,
        const float* __restrict__ rot,
        const float* __restrict__ feat,
        const float* __restrict__ opac,
        int n) {
    // Signal dependent launch immediately: finalize's grid ramps concurrently.
    asm volatile("griddepcontrol.launch_dependents;");

    // Half-warp per gaussian: lanes 0-15 -> g0, lanes 16-31 -> g1.
    int warp = (blockIdx.x * blockDim.x + threadIdx.x) >> 5;
    int lane = threadIdx.x & 31;
    int g = warp * 2 + (lane >> 4);
    if (g >= n) return;

    // ---- ALL input loads issued up front (MLP=5+, one memory epoch) ----
    float2 xy = ((const float2*)xyz)[g];
    float2 sc = ((const float2*)scaling)[g];
    float rt  = rot[g];
    float op  = opac[g];
    float f0  = feat[3 * g];
    float f1  = feat[3 * g + 1];
    float f2  = feat[3 * g + 2];

    // Per-gaussian prep with MUFU-direct intrinsics.
    // tanh(x) = 1 - 2/(exp(2x)+1)
    float mx = 1.0f - __fdividef(2.0f, __expf(2.0f * xy.x) + 1.0f);
    float my = 1.0f - __fdividef(2.0f, __expf(2.0f * xy.y) + 1.0f);
    float sx = fabsf(sc.x + 0.5f);
    float sy = fabsf(sc.y + 0.5f);
    // sigmoid(r) * 2pi
    float theta = __fdividef(TWO_PI, 1.0f + __expf(-rt));

    float cx = 0.5f * ((mx + 1.0f) * (float)W - 1.0f);
    float cy = 0.5f * ((my + 1.0f) * (float)H - 1.0f);

    float sth, cth;
    __sincosf(theta, &sth, &cth);
    float sx2 = sx * sx;
    float sy2 = sy * sy;
    float a = cth * cth * sx2 + sth * sth * sy2;
    float b = cth * sth * (sx2 - sy2);
    float c = sth * sth * sx2 + cth * cth * sy2;
    float det = a * c - b * b;
    float tmax = __logf(op * 255.0f);   // alpha > 1/255 <=> sigma < tmax
    if (!(det > 0.0f) || !(tmax > 0.0f)) return;

    float inv_det = __fdividef(1.0f, fmaxf(det, 1e-12f));
    float hA = 0.5f * c * inv_det;      // 0.5*A
    float B  = -b * inv_det;
    float hC = 0.5f * a * inv_det;      // 0.5*C

    // a,c <= 2.25, tmax <= ln(255) => rx,ry <= ~6.1 => bbox width <= 13 < 16
    float rx = sqrtf(2.0f * tmax * a) + 1.0f;
    float ry = sqrtf(2.0f * tmax * c) + 1.0f;

    int x0 = max(0, (int)ceilf(cx - rx));
    int x1 = min(W - 1, (int)floorf(cx + rx));
    int y0 = max(0, (int)ceilf(cy - ry));
    int y1 = min(H - 1, (int)floorf(cy + ry));
    if (x1 < x0 || y1 < y0) return;

    float c0 = op * f0;
    float c1 = op * f1;
    float c2 = op * f2;

    // lane&15 indexes x within this gaussian's bbox; loop rows one at a time.
    int px = x0 + (lane & 15);
    float dx = cx - (float)px;
    float sxx = hA * dx * dx;
    float bdx = B * dx;
    bool xin = (px <= x1);

    for (int py = y0; py <= y1; py++) {
        float dy = cy - (float)py;
        float sigma = fmaf(hC, dy, bdx) * dy + sxx;
        float w = __expf(-sigma);
        float alpha = op * w;
        if (xin && sigma >= 0.0f && alpha > ALPHA_THRESH) {
            float4* dst = &g_accum[py * W + px];
            asm volatile("red.global.add.v4.f32 [%0], {%1, %2, %3, %4};"
                         :: "l"(dst), "f"(w * c0), "f"(w * c1),
                            "f"(w * c2), "f"(0.0f)
                         : "memory");
        }
    }
}

__global__ __launch_bounds__(256) void finalize_kernel(float* __restrict__ out) {
    int t = blockIdx.x * blockDim.x + threadIdx.x;   // 65536 threads, 4 px each

    // wait until splat's memory is visible
    asm volatile("griddepcontrol.wait;");

    // 4 independent L2-only loads up front -> MLP = 4 per thread
    float4 v0 = __ldcg(&g_accum[t]);
    float4 v1 = __ldcg(&g_accum[t + QW]);
    float4 v2 = __ldcg(&g_accum[t + 2 * QW]);
    float4 v3 = __ldcg(&g_accum[t + 3 * QW]);

    float4 z = make_float4(0.0f, 0.0f, 0.0f, 0.0f);
    g_accum[t]          = z;           // re-arm for next graph replay
    g_accum[t + QW]     = z;
    g_accum[t + 2 * QW] = z;
    g_accum[t + 3 * QW] = z;

    #define CLAMP(x) fminf(fmaxf((x), 0.0f), 1.0f)
    __stcs(&out[t],                    CLAMP(v0.x));
    __stcs(&out[t + QW],               CLAMP(v1.x));
    __stcs(&out[t + 2 * QW],           CLAMP(v2.x));
    __stcs(&out[t + 3 * QW],           CLAMP(v3.x));

    __stcs(&out[HW + t],               CLAMP(v0.y));
    __stcs(&out[HW + t + QW],          CLAMP(v1.y));
    __stcs(&out[HW + t + 2 * QW],      CLAMP(v2.y));
    __stcs(&out[HW + t + 3 * QW],      CLAMP(v3.y));

    __stcs(&out[2 * HW + t],           CLAMP(v0.z));
    __stcs(&out[2 * HW + t + QW],      CLAMP(v1.z));
    __stcs(&out[2 * HW + t + 2 * QW],  CLAMP(v2.z));
    __stcs(&out[2 * HW + t + 3 * QW],  CLAMP(v3.z));
    #undef CLAMP
}

extern "C" void kernel_launch(void* const* d_in, const int* in_sizes, int n_in,
                              void* d_out, int out_size) {
    const float* xyz     = (const float*)d_in[0];  // (N,2)
    const float* scaling = (const float*)d_in[1];  // (N,2)
    const float* rot     = (const float*)d_in[2];  // (N,1)
    const float* feat    = (const float*)d_in[3];  // (N,3)
    const float* opac    = (const float*)d_in[4];  // (N,1)
    float* out = (float*)d_out;                     // (1,3,512,512)

    int n = in_sizes[0] / 2;

    int blocks = (n + 15) / 16;                     // 8 warps/block, 2 gaussians/warp
    splat_kernel<<<blocks, 256>>>(xyz, scaling, rot, feat, opac, n);

    // finalize launched as a programmatic dependent: ramps while splat runs
    cudaLaunchConfig_t cfg = {};
    cfg.gridDim  = dim3(QW / 256);                  // 256 blocks
    cfg.blockDim = dim3(256);
    cfg.dynamicSmemBytes = 0;
    cfg.stream = 0;
    cudaLaunchAttribute attr[1];
    attr[0].id = cudaLaunchAttributeProgrammaticStreamSerialization;
    attr[0].val.programmaticStreamSerializationAllowed = 1;
    cfg.attrs = attr;
    cfg.numAttrs = 1;
    cudaLaunchKernelEx(&cfg, finalize_kernel, out);
}